// round 9
// baseline (speedup 1.0000x reference)
#include <cuda_runtime.h>
#include <cstdint>
#include <float.h>

// Problem constants
#define Bn    8
#define Nn    256
#define Dd    128
#define MIDn  128
#define FEATn 256   // 2*D
#define NTOT  (Bn * Nn)     // 2048 (b,j) tiles
#define GRID  296           // persistent: 2 CTAs x 148 SMs

// Scratch (device globals; no runtime allocation allowed)
__device__ float g_msg1[Bn * Nn * MIDn];
__device__ float g_msg2[Bn * Nn * MIDn];
__device__ float g_msgg[Bn * MIDn];
__device__ float g_base[Bn * Nn * MIDn];
__device__ unsigned g_WeTpack[MIDn * Dd];       // We^T fragment-packed (tf32 bits)

// ---------------- PTX helpers (arch-agnostic, sm_80+) --------------------
__device__ __forceinline__ uint32_t smem_u32(const void* p) {
    uint32_t a;
    asm("{ .reg .u64 t; cvta.to.shared.u64 t, %1; cvt.u32.u64 %0, t; }"
        : "=r"(a) : "l"(p));
    return a;
}
__device__ __forceinline__ void cp16(uint32_t dst, const void* src) {
    asm volatile("cp.async.cg.shared.global [%0], [%1], 16;"
                 :: "r"(dst), "l"(src) : "memory");
}
__device__ __forceinline__ void cp_commit() {
    asm volatile("cp.async.commit_group;" ::: "memory");
}
template <int N> __device__ __forceinline__ void cp_wait() {
    asm volatile("cp.async.wait_group %0;" :: "n"(N) : "memory");
}
__device__ __forceinline__ unsigned tf32r(float x) {
    unsigned u;
    asm("cvt.rna.tf32.f32 %0, %1;" : "=r"(u) : "f"(x));
    return u;
}
__device__ __forceinline__ void mma8(float* c, uint4 a, unsigned b0, unsigned b1) {
    asm volatile(
        "mma.sync.aligned.m16n8k8.row.col.f32.tf32.tf32.f32 "
        "{%0,%1,%2,%3},{%4,%5,%6,%7},{%8,%9},{%0,%1,%2,%3};"
        : "+f"(c[0]), "+f"(c[1]), "+f"(c[2]), "+f"(c[3])
        : "r"(a.x), "r"(a.y), "r"(a.z), "r"(a.w), "r"(b0), "r"(b1));
}

// ---------------- smem layout (bytes) ------------------------------------
#define EPADB    544                        // 136 floats: LDS.64 CF
#define ECHUNKB  (32 * EPADB)               // 17408
#define M2PADB   528                        // 132 floats: LDS.32 CF
#define M2CHUNKB (32 * M2PADB)              // 16896
#define SM_E0    0
#define SM_E1    ECHUNKB
#define SM_M0    (2 * ECHUNKB)              // 34816
#define SM_M1    (SM_M0 + M2CHUNKB)         // 51712
#define SM_IDX0  (SM_M1 + M2CHUNKB)         // 68608 (256 ints)
#define SM_IDX1  (SM_IDX0 + 1024)           // 69632 (256 ints)
#define SM_CNT0  (SM_IDX1 + 1024)           // 70656
#define SM_CNT1  (SM_CNT0 + 4)
#define SM_BEST  (SM_CNT1 + 124)            // 70784 (128 floats)
#define SM_TOTAL (SM_BEST + 512)            // 71296

// ========================================================================
// Fused aux kernel (512 threads/block, 296 blocks):
//   [0,256)   : prep (msg1,msg2,base)  m=tid&127, f-quarter h=tid>>7
//   [256,288) : pack We^T A-fragments  (k-relabel: slot t -> 2t,2t+1)
//   [288,296) : msgg (tid<128)
// ========================================================================
__global__ __launch_bounds__(512) void aux_kernel(
    const float* __restrict__ hidden, const float* __restrict__ nfeat,
    const float* __restrict__ gfeat,
    const float* __restrict__ W1, const float* __restrict__ b1,
    const float* __restrict__ W2, const float* __restrict__ b2,
    const float* __restrict__ We,
    const float* __restrict__ Wg, const float* __restrict__ bg,
    const float* __restrict__ Wo1, const float* __restrict__ bo1,
    const float* __restrict__ bo2)
{
    const int tid = threadIdx.x;
    if (blockIdx.x >= 288) {                       // ---- msgg ----
        if (tid < 128) {
            const int b = blockIdx.x - 288, m = tid;
            float acc = bg[m];
            #pragma unroll 8
            for (int k = 0; k < Dd; k++)
                acc = fmaf(gfeat[b * Dd + k], __ldg(&Wg[k * MIDn + m]), acc);
            g_msgg[b * MIDn + m] = acc;
        }
        return;
    }
    if (blockIdx.x >= 256) {                       // ---- A pack ----
        const int idx = (blockIdx.x - 256) * 512 + tid;   // 0..16383
        const int blk = idx >> 7;                  // mtg*16 + kt (mtg: 16-row)
        const int mtg = blk >> 4, kt = blk & 15;
        const int l = (idx >> 2) & 31, e = idx & 3;
        const int m = mtg * 16 + (l >> 2) + (e & 1) * 8;
        const int k = kt * 8 + 2 * (l & 3) + (e >> 1);
        g_WeTpack[idx] = tf32r(We[k * MIDn + m]);
        return;
    }
    // ---- prep: 8 rows, f split 4 ways ----
    __shared__ float fs[8 * FEATn];
    __shared__ float red[3][3 * 1024];
    const int m = tid & 127, h = tid >> 7;
    const int row0 = blockIdx.x * 8;

    for (int idx = tid; idx < 8 * FEATn; idx += 512) {
        int r = idx >> 8, c = idx & 255;
        fs[idx] = (c < Dd) ? nfeat[(row0 + r) * Dd + c]
                           : hidden[(row0 + r) * Dd + (c - Dd)];
    }
    __syncthreads();

    float a1[8], a2[8], ao[8];
    #pragma unroll
    for (int r = 0; r < 8; r++) { a1[r] = 0.f; a2[r] = 0.f; ao[r] = 0.f; }

    const int fbase = h * 64;
    #pragma unroll 4
    for (int ff = 0; ff < 64; ff++) {
        const int f = fbase + ff;
        const float w1 = __ldg(&W1[f * MIDn + m]);
        const float w2 = __ldg(&W2[f * MIDn + m]);
        const float wo = __ldg(&Wo1[f * MIDn + m]);
        #pragma unroll
        for (int r = 0; r < 8; r++) {
            const float s = fs[r * FEATn + f];
            a1[r] = fmaf(s, w1, a1[r]);
            a2[r] = fmaf(s, w2, a2[r]);
            ao[r] = fmaf(s, wo, ao[r]);
        }
    }
    if (h > 0) {
        #pragma unroll
        for (int r = 0; r < 8; r++) {
            red[h - 1][0 * 1024 + r * 128 + m] = a1[r];
            red[h - 1][1 * 1024 + r * 128 + m] = a2[r];
            red[h - 1][2 * 1024 + r * 128 + m] = ao[r];
        }
    }
    __syncthreads();
    if (h == 0) {
        const float bb1 = b1[m], bb2 = b2[m], bbo = bo1[m] + bo2[m];
        #pragma unroll
        for (int r = 0; r < 8; r++) {
            const int row = row0 + r;
            const int o = r * 128 + m;
            g_msg1[row * MIDn + m] = a1[r] + red[0][o] + red[1][o]
                                   + red[2][o] + bb1;
            g_msg2[row * MIDn + m] = a2[r] + red[0][1024 + o] + red[1][1024 + o]
                                   + red[2][1024 + o] + bb2;
            g_base[row * MIDn + m] = ao[r] + red[0][2048 + o] + red[1][2048 + o]
                                   + red[2][2048 + o] + bbo;
        }
    }
}

// ========================================================================
// Persistent main kernel, 256 threads / 8 warps, warp m-tile = 16.
// acc initialized with (msg2 + cst) via mma C-input; fold = max(acc*adj).
// ========================================================================
__device__ __forceinline__ void stage_chunk(uint32_t sb, const float* ebj,
                                            const float* m2g,
                                            const int* idxsm, int c,
                                            int w, int l)
{
    const uint32_t ebuf = sb + ((c & 1) ? SM_E1 : SM_E0);
    const uint32_t mbuf = sb + ((c & 1) ? SM_M1 : SM_M0);
    #pragma unroll
    for (int rr = 0; rr < 4; rr++) {
        const int r = w + rr * 8;                 // 0..31
        const long i = idxsm[c * 32 + r];
        cp16(ebuf + r * EPADB + l * 16, ebj + i * (Nn * Dd) + l * 4);
        cp16(mbuf + r * M2PADB + l * 16, m2g + i * MIDn + l * 4);
    }
}

__device__ __forceinline__ int build_list(const float* __restrict__ adjcol,
                                          int* idxd, int* cntd,
                                          int tid, int w, int l)
{
    if (tid == 0) *cntd = 0;
    __syncthreads();
    {
        const int i = w * 32 + l;                 // 8 warps cover 256
        const float a = adjcol[(long)i * Nn];
        const unsigned mask = __ballot_sync(0xFFFFFFFFu, a != 0.f);
        int basep = 0;
        if (l == 0) basep = atomicAdd(cntd, __popc(mask));
        basep = __shfl_sync(0xFFFFFFFFu, basep, 0);
        if (a != 0.f) idxd[basep + __popc(mask & ((1u << l) - 1))] = i;
    }
    __syncthreads();
    const int cnt = *cntd;
    for (int s = cnt + tid; s < 256; s += 256) idxd[s] = 0;   // pads
    __syncthreads();
    return cnt;
}

__global__ __launch_bounds__(256, 2) void main_kernel(
    const float* __restrict__ efeat, const float* __restrict__ adj,
    const float* __restrict__ be,    const float* __restrict__ Wo2,
    float* __restrict__ out)
{
    extern __shared__ __align__(16) char smem[];
    const uint32_t sb = smem_u32(smem);
    const int tid = threadIdx.x;
    const int w = tid >> 5, l = tid & 31, g = l >> 2, t = l & 3;

    int* idxb[2] = { (int*)(smem + SM_IDX0), (int*)(smem + SM_IDX1) };
    int* cntb[2] = { (int*)(smem + SM_CNT0), (int*)(smem + SM_CNT1) };
    float* bestsm = (float*)(smem + SM_BEST);

    const int mw = w * 16;                        // warp's m-tile base
    const int mlo = mw + g, mhi = mw + g + 8;     // this thread's 2 m rows

    // A fragments for this warp's 16-row m-tile -> 16 uint4 (64 regs)
    uint4 A[16];
    #pragma unroll
    for (int kt = 0; kt < 16; kt++)
        A[kt] = *(const uint4*)(g_WeTpack + ((w * 16 + kt) << 7) + (l << 2));

    int it = blockIdx.x;
    int buf = 0;
    int cnt_cur;
    {   // first tile: list + prefill
        const int b = it >> 8, j = it & 255;
        cnt_cur = build_list(adj + (long)b * Nn * Nn + j,
                             idxb[0], cntb[0], tid, w, l);
        const float* ebj = efeat + (long)b * (Nn * Nn * Dd) + (long)j * Dd;
        const float* m2g = g_msg2 + ((long)b << 15);
        const int nc = (cnt_cur + 31) >> 5;
        if (nc > 0) stage_chunk(sb, ebj, m2g, idxb[0], 0, w, l);
        cp_commit();
        if (nc > 1) stage_chunk(sb, ebj, m2g, idxb[0], 1, w, l);
        cp_commit();
    }

    while (it < NTOT) {
        const int b = it >> 8, j = it & 255;
        const float* ebj = efeat + (long)b * (Nn * Nn * Dd) + (long)j * Dd;
        const float* m2g = g_msg2 + ((long)b << 15);
        const int* idxc = idxb[buf];
        const int cnt = cnt_cur;
        const int nc = (cnt + 31) >> 5;

        const float clo = g_msg1[it * MIDn + mlo] + g_msgg[b * MIDn + mlo]
                        + be[mlo];
        const float chi = g_msg1[it * MIDn + mhi] + g_msgg[b * MIDn + mhi]
                        + be[mhi];
        float blo = -FLT_MAX, bhi = -FLT_MAX;

        #pragma unroll 1
        for (int c = 0; c < nc; c++) {
            cp_wait<1>();
            __syncthreads();
            const char* eb = smem + ((c & 1) ? SM_E1 : SM_E0);
            const float* m2s = (const float*)(smem + ((c & 1) ? SM_M1 : SM_M0));

            // acc init = msg2 + cst (exact; adds move into the mma C chain)
            float acc[4][4];
            #pragma unroll
            for (int nt = 0; nt < 4; nt++) {
                const int il = nt * 8 + 2 * t;
                acc[nt][0] = m2s[il * 132 + mlo] + clo;
                acc[nt][1] = m2s[(il + 1) * 132 + mlo] + clo;
                acc[nt][2] = m2s[il * 132 + mhi] + chi;
                acc[nt][3] = m2s[(il + 1) * 132 + mhi] + chi;
            }

            #pragma unroll
            for (int kt = 0; kt < 16; kt++) {
                #pragma unroll
                for (int nt = 0; nt < 4; nt++) {
                    const float2 bv = *(const float2*)(eb
                                       + (nt * 8 + g) * EPADB + kt * 32 + t * 8);
                    mma8(acc[nt], A[kt],
                         __float_as_uint(bv.x), __float_as_uint(bv.y));
                }
            }

            #pragma unroll
            for (int nt = 0; nt < 4; nt++) {
                const int slot = c * 32 + nt * 8 + 2 * t;
                const float aj0 = (slot < cnt) ? 1.f : 0.f;
                const float aj1 = (slot + 1 < cnt) ? 1.f : 0.f;
                blo = fmaxf(blo, fmaxf(acc[nt][0] * aj0, acc[nt][1] * aj1));
                bhi = fmaxf(bhi, fmaxf(acc[nt][2] * aj0, acc[nt][3] * aj1));
            }
            __syncthreads();
            if (c + 2 < nc) stage_chunk(sb, ebj, m2g, idxc, c + 2, w, l);
            cp_commit();
        }

        // --- splice: build + prefill NEXT tile before epilogue ---
        const int itn = it + GRID;
        if (itn < NTOT) {
            const int bn = itn >> 8, jn = itn & 255;
            cnt_cur = build_list(adj + (long)bn * Nn * Nn + jn,
                                 idxb[buf ^ 1], cntb[buf ^ 1], tid, w, l);
            const float* ebjn = efeat + (long)bn * (Nn * Nn * Dd)
                                + (long)jn * Dd;
            const float* m2gn = g_msg2 + ((long)bn << 15);
            const int ncn = (cnt_cur + 31) >> 5;
            if (ncn > 0) stage_chunk(sb, ebjn, m2gn, idxb[buf ^ 1], 0, w, l);
            cp_commit();
            if (ncn > 1) stage_chunk(sb, ebjn, m2gn, idxb[buf ^ 1], 1, w, l);
            cp_commit();
        }

        // --- epilogue (overlaps next tile's fill) ---
        if (cnt < Nn) { blo = fmaxf(blo, 0.f); bhi = fmaxf(bhi, 0.f); }
        blo = fmaxf(blo, __shfl_xor_sync(0xFFFFFFFFu, blo, 1));
        blo = fmaxf(blo, __shfl_xor_sync(0xFFFFFFFFu, blo, 2));
        bhi = fmaxf(bhi, __shfl_xor_sync(0xFFFFFFFFu, bhi, 1));
        bhi = fmaxf(bhi, __shfl_xor_sync(0xFFFFFFFFu, bhi, 2));
        __syncthreads();
        if (t == 0) { bestsm[mlo] = blo; bestsm[mhi] = bhi; }
        __syncthreads();

        if (tid < 128) {
            float o = g_base[it * MIDn + tid];
            #pragma unroll 8
            for (int k = 0; k < MIDn; k++)
                o = fmaf(bestsm[k], __ldg(&Wo2[(k << 7) + tid]), o);
            out[it * MIDn + tid] = o;
        }

        buf ^= 1;
        it = itn;
    }
}

// ========================================================================
extern "C" void kernel_launch(void* const* d_in, const int* in_sizes, int n_in,
                              void* d_out, int out_size)
{
    const float* hidden = (const float*)d_in[0];
    const float* nfeat  = (const float*)d_in[1];
    const float* efeat  = (const float*)d_in[2];
    const float* gfeat  = (const float*)d_in[3];
    const float* adj    = (const float*)d_in[4];
    const float* W1  = (const float*)d_in[5];
    const float* b1  = (const float*)d_in[6];
    const float* W2  = (const float*)d_in[7];
    const float* b2  = (const float*)d_in[8];
    const float* We  = (const float*)d_in[9];
    const float* be  = (const float*)d_in[10];
    const float* Wg  = (const float*)d_in[11];
    const float* bg  = (const float*)d_in[12];
    const float* Wo1 = (const float*)d_in[13];
    const float* bo1 = (const float*)d_in[14];
    const float* Wo2 = (const float*)d_in[15];
    const float* bo2 = (const float*)d_in[16];
    float* out = (float*)d_out;

    static int smem_set = 0;
    if (!smem_set) {
        cudaFuncSetAttribute(main_kernel,
                             cudaFuncAttributeMaxDynamicSharedMemorySize,
                             SM_TOTAL);
        smem_set = 1;
    }

    aux_kernel<<<296, 512>>>(hidden, nfeat, gfeat, W1, b1, W2, b2, We,
                             Wg, bg, Wo1, bo1, bo2);
    main_kernel<<<GRID, 256, SM_TOTAL>>>(efeat, adj, be, Wo2, out);
}